// round 2
// baseline (speedup 1.0000x reference)
#include <cuda_runtime.h>
#include <cuda_bf16.h>

// Problem constants (fixed by the dataset)
#define BB      32      // batch
#define SS      64      // S
#define DD      8       // D
#define NEIDX   512     // S*D distinct per-edge weight indices
#define EMAX    150000  // number of edges
#define NW      8       // warps per CTA in edge-MLP kernel

// ---------------- device scratch (no allocations allowed) ----------------
__device__ int   g_bin_cnt[NEIDX];
__device__ int   g_bin_start[NEIDX + 1];
__device__ int   g_cursor[NEIDX];
__device__ int   g_sorted[EMAX];                 // packed: c0 | (c1<<5)
__device__ float g_sums[NEIDX * BB * 32];        // [e][b][o]
__device__ int   g_counts[NEIDX * BB];           // [e][b]

// ---------------- K0: zero bin counters ----------------
__global__ void k_zero() {
    int t = blockIdx.x * blockDim.x + threadIdx.x;
    if (t < NEIDX) g_bin_cnt[t] = 0;
}

// ---------------- K1: histogram of eidx ----------------
__global__ void k_hist(const int4* __restrict__ inc, int E) {
    int i = blockIdx.x * blockDim.x + threadIdx.x;
    if (i < E) {
        int4 r = inc[i];                 // {c0, c1, c2, c3}
        atomicAdd(&g_bin_cnt[r.z * DD + r.w], 1);
    }
}

// ---------------- K2: exclusive scan of 512 bins (single block) ----------------
__global__ void k_scan() {
    __shared__ int s[NEIDX];
    int t = threadIdx.x;
    int v = g_bin_cnt[t];
    s[t] = v;
    __syncthreads();
    for (int off = 1; off < NEIDX; off <<= 1) {
        int x = (t >= off) ? s[t - off] : 0;
        __syncthreads();
        s[t] += x;
        __syncthreads();
    }
    g_bin_start[t + 1] = s[t];
    if (t == 0) g_bin_start[0] = 0;
    g_cursor[t] = s[t] - v;              // exclusive prefix = scatter cursor
}

// ---------------- K3: scatter edges into eidx bins ----------------
__global__ void k_scatter(const int4* __restrict__ inc, int E) {
    int i = blockIdx.x * blockDim.x + threadIdx.x;
    if (i < E) {
        int4 r = inc[i];
        int e = r.z * DD + r.w;
        int pos = atomicAdd(&g_cursor[e], 1);
        g_sorted[pos] = r.x | (r.y << 5);    // c0 (5 bits) | c1 (10 bits)
    }
}

// ---------------- K4: edge MLP + SMEM segment reduction ----------------
// One CTA per eidx. Weights staged in SMEM once (kills ~900 MB of L2 traffic).
// One warp per edge; lane = output channel. Segment sums live in per-warp
// SMEM accumulators (c0 in [0,32)) -> zero global atomics.
__global__ __launch_bounds__(NW * 32) void k_mlp_in(
    const float* __restrict__ nodes,
    const float* __restrict__ W0, const float* __restrict__ b0,
    const float* __restrict__ W1, const float* __restrict__ b1)
{
    __shared__ float sW0[16 * 32];           // transposed [i][o]
    __shared__ float sW1[32 * 32];           // transposed [i][o]
    __shared__ float sb0[32], sb1[32];
    __shared__ float acc[NW][BB * 32];       // per-warp [c0][o]
    __shared__ int   cnt[NW][BB];

    int e    = blockIdx.x;
    int tid  = threadIdx.x;
    int warp = tid >> 5, lane = tid & 31;

    for (int t = tid; t < 512; t += NW * 32) {
        int o = t >> 4, i = t & 15;
        sW0[i * 32 + o] = W0[e * 512 + t];   // W0 global: [e][o][i] (32x16)
    }
    for (int t = tid; t < 1024; t += NW * 32) {
        int o = t >> 5, i = t & 31;
        sW1[i * 32 + o] = W1[e * 1024 + t];  // W1 global: [e][o][i] (32x32)
    }
    if (tid < 32) { sb0[tid] = b0[e * 32 + tid]; sb1[tid] = b1[e * 32 + tid]; }
    for (int t = tid; t < NW * BB * 32; t += NW * 32) (&acc[0][0])[t] = 0.f;
    for (int t = tid; t < NW * BB;      t += NW * 32) (&cnt[0][0])[t] = 0;
    __syncthreads();

    int c2    = e >> 3;                      // c2 is constant within a bin
    int start = g_bin_start[e];
    int end   = g_bin_start[e + 1];
    float* myacc = acc[warp];
    int*   mycnt = cnt[warp];

    for (int j = start + warp; j < end; j += NW) {
        int packed = g_sorted[j];
        int c0 = packed & 31;
        int c1 = packed >> 5;
        const float* xp = nodes + (c1 * SS + c2) * 16;
        float xv = (lane < 16) ? xp[lane] : 0.f;

        // layer 1: h[lane] = relu(sum_i W0[lane][i]*x[i] + b0[lane])
        float h = 0.f;
        #pragma unroll
        for (int i = 0; i < 16; i++)
            h = fmaf(sW0[i * 32 + lane], __shfl_sync(0xffffffffu, xv, i), h);
        h = fmaxf(h + sb0[lane], 0.f);

        // layer 2: g[lane] = relu(sum_i W1[lane][i]*h[i] + b1[lane])
        float g = 0.f;
        #pragma unroll
        for (int i = 0; i < 32; i++)
            g = fmaf(sW1[i * 32 + lane], __shfl_sync(0xffffffffu, h, i), g);
        g = fmaxf(g + sb1[lane], 0.f);

        myacc[c0 * 32 + lane] += g;          // conflict-free: 32 consecutive floats
        if (lane == 0) mycnt[c0]++;
    }
    __syncthreads();

    // reduce across warps and store (bins disjoint -> plain stores)
    for (int t = tid; t < BB * 32; t += NW * 32) {
        float s = 0.f;
        #pragma unroll
        for (int w = 0; w < NW; w++) s += acc[w][t];
        g_sums[e * BB * 32 + t] = s;
    }
    if (tid < BB) {
        int s = 0;
        #pragma unroll
        for (int w = 0; w < NW; w++) s += cnt[w][tid];
        g_counts[e * BB + tid] = s;
    }
}

// ---------------- K5: mean + output MLP ----------------
// One CTA per eidx. Fuses segment-mean (with zero-count handling) with the
// two output layers. Writes every output element (d_out is poisoned).
__global__ __launch_bounds__(256) void k_mlp_out(
    const float* __restrict__ W0, const float* __restrict__ b0,
    const float* __restrict__ W1, const float* __restrict__ b1,
    float* __restrict__ out)
{
    __shared__ float ef[BB * 32];
    __shared__ float sW0[32 * 32];           // transposed [i][o]
    __shared__ float hh[BB * 32];
    __shared__ float sW1[32 * 16];           // transposed [i][o]
    __shared__ float sb0[32], sb1[16];
    __shared__ int   scnt[BB];

    int e = blockIdx.x;
    int tid = threadIdx.x;

    if (tid < BB) scnt[tid] = g_counts[e * BB + tid];
    for (int t = tid; t < 1024; t += 256) {
        int o = t >> 5, i = t & 31;
        sW0[i * 32 + o] = W0[e * 1024 + t];  // out_core0: [e][o][i] (32x32)
    }
    for (int t = tid; t < 512; t += 256) {
        int o = t >> 5, i = t & 31;
        sW1[i * 16 + o] = W1[e * 512 + t];   // out_core1: [e][o][i] (16x32)
    }
    if (tid < 32) sb0[tid] = b0[e * 32 + tid];
    if (tid < 16) sb1[tid] = b1[e * 16 + tid];
    __syncthreads();

    for (int t = tid; t < 1024; t += 256) {
        int b_ = t >> 5;
        int c = scnt[b_];
        ef[t] = (c > 0) ? g_sums[e * BB * 32 + t] / (float)c : 0.f;
    }
    __syncthreads();

    for (int t = tid; t < 1024; t += 256) {
        int b_ = t >> 5, o = t & 31;
        float s = sb0[o];
        #pragma unroll
        for (int i = 0; i < 32; i++)
            s = fmaf(sW0[i * 32 + o], ef[b_ * 32 + i], s);
        hh[t] = fmaxf(s, 0.f);
    }
    __syncthreads();

    for (int t = tid; t < BB * 16; t += 256) {
        int b_ = t >> 4, o = t & 15;
        float s = sb1[o];
        #pragma unroll
        for (int i = 0; i < 32; i++)
            s = fmaf(sW1[i * 16 + o], hh[b_ * 32 + i], s);
        out[(b_ * NEIDX + e) * 16 + o] = fmaxf(s, 0.f);
    }
}

// ---------------- launch ----------------
extern "C" void kernel_launch(void* const* d_in, const int* in_sizes, int n_in,
                              void* d_out, int out_size) {
    const float* nodes = (const float*)d_in[0];
    const float* ic0   = (const float*)d_in[1];
    const float* ib0   = (const float*)d_in[2];
    const float* ic1   = (const float*)d_in[3];
    const float* ib1   = (const float*)d_in[4];
    const float* oc0   = (const float*)d_in[5];
    const float* ob0   = (const float*)d_in[6];
    const float* oc1   = (const float*)d_in[7];
    const float* ob1   = (const float*)d_in[8];
    const int4*  inc   = (const int4*)d_in[9];
    int E = in_sizes[9] / 4;
    float* out = (float*)d_out;

    k_zero<<<2, 256>>>();
    k_hist<<<(E + 255) / 256, 256>>>(inc, E);
    k_scan<<<1, NEIDX>>>();
    k_scatter<<<(E + 255) / 256, 256>>>(inc, E);
    k_mlp_in<<<NEIDX, NW * 32>>>(nodes, ic0, ib0, ic1, ib1);
    k_mlp_out<<<NEIDX, 256>>>(oc0, ob0, oc1, ob1, out);
}

// round 3
// speedup vs baseline: 1.3638x; 1.3638x over previous
#include <cuda_runtime.h>
#include <cuda_bf16.h>

#define BB      32      // batch
#define SS      64      // S
#define DD      8       // D
#define NEIDX   512     // S*D distinct weight indices
#define EMAX    150000
#define NW      8       // warps per CTA in fused kernel
#define NBIN_CTAS 64    // CTAs for hist/scatter

// ---------------- device scratch ----------------
__device__ int g_bin_cnt[NEIDX];
__device__ int g_bin_start[NEIDX + 1];
__device__ int g_cursor[NEIDX];
__device__ int g_sorted[EMAX];            // packed: c0 | (c1<<5)

// ---------------- K0: zero bin counters ----------------
__global__ void k_zero() {
    g_bin_cnt[threadIdx.x] = 0;
}

// ---------------- K1: CTA-aggregated histogram ----------------
__global__ __launch_bounds__(512) void k_hist(const int4* __restrict__ inc, int E) {
    __shared__ int sh[NEIDX];
    int tid = threadIdx.x;
    sh[tid] = 0;
    __syncthreads();
    int per = (E + gridDim.x - 1) / gridDim.x;
    int beg = blockIdx.x * per;
    int end = min(beg + per, E);
    for (int i = beg + tid; i < end; i += 512) {
        int4 r = inc[i];
        atomicAdd(&sh[r.z * DD + r.w], 1);
    }
    __syncthreads();
    if (sh[tid]) atomicAdd(&g_bin_cnt[tid], sh[tid]);
}

// ---------------- K2: exclusive scan (single block) ----------------
__global__ void k_scan() {
    __shared__ int s[NEIDX];
    int t = threadIdx.x;
    int v = g_bin_cnt[t];
    s[t] = v;
    __syncthreads();
    for (int off = 1; off < NEIDX; off <<= 1) {
        int x = (t >= off) ? s[t - off] : 0;
        __syncthreads();
        s[t] += x;
        __syncthreads();
    }
    g_bin_start[t + 1] = s[t];
    if (t == 0) g_bin_start[0] = 0;
    g_cursor[t] = s[t] - v;               // exclusive prefix
}

// ---------------- K3: CTA-aggregated scatter ----------------
__global__ __launch_bounds__(512) void k_scatter(const int4* __restrict__ inc, int E) {
    __shared__ int sh[NEIDX];   // local histogram, then unused
    __shared__ int sc[NEIDX];   // local running cursor (global base)
    int tid = threadIdx.x;
    sh[tid] = 0;
    __syncthreads();
    int per = (E + gridDim.x - 1) / gridDim.x;
    int beg = blockIdx.x * per;
    int end = min(beg + per, E);
    for (int i = beg + tid; i < end; i += 512) {
        int4 r = inc[i];
        atomicAdd(&sh[r.z * DD + r.w], 1);
    }
    __syncthreads();
    int n = sh[tid];
    sc[tid] = n ? atomicAdd(&g_cursor[tid], n) : 0;   // reserve global range
    __syncthreads();
    for (int i = beg + tid; i < end; i += 512) {
        int4 r = inc[i];
        int b = r.z * DD + r.w;
        int pos = atomicAdd(&sc[b], 1);               // SMEM cursor
        g_sorted[pos] = r.x | (r.y << 5);
    }
}

// ---------------- K4: fused edge MLP + segment mean + output MLP ----------------
// One CTA per eidx. Edge-per-lane: each lane computes the full 2-layer MLP
// for one edge in registers; weights broadcast from SMEM (LDS.128, N=1).
// Accumulation: per-warp acc[o][c0] (bank = c0 -> conflict-free across lanes)
// via shared-float atomics. Then mean + 2-layer output MLP in the same CTA.
__global__ __launch_bounds__(NW * 32) void k_fused(
    const float* __restrict__ nodes,
    const float* __restrict__ W0,  const float* __restrict__ b0,
    const float* __restrict__ W1,  const float* __restrict__ b1,
    const float* __restrict__ oW0, const float* __restrict__ ob0,
    const float* __restrict__ oW1, const float* __restrict__ ob1,
    float* __restrict__ out)
{
    __shared__ float sW0[512];            // in_core0 [o][i] 32x16 (row-major, broadcast reads)
    __shared__ float sW1[1024];           // in_core1 [o][i] 32x32
    __shared__ float sb0[32], sb1[32];
    __shared__ float acc[NW][32 * BB];    // [warp][o][c0]
    __shared__ int   cnt[NW][BB];
    __shared__ int   scnt[BB];
    __shared__ float ef[BB * 32];         // [b][i]
    __shared__ float hh[BB * 32];         // [b][o]

    int e    = blockIdx.x;
    int tid  = threadIdx.x;
    int warp = tid >> 5, lane = tid & 31;

    for (int t = tid; t < 512;  t += NW * 32) sW0[t] = W0[e * 512 + t];
    for (int t = tid; t < 1024; t += NW * 32) sW1[t] = W1[e * 1024 + t];
    if (tid < 32) { sb0[tid] = b0[e * 32 + tid]; sb1[tid] = b1[e * 32 + tid]; }
    for (int t = tid; t < NW * 32 * BB; t += NW * 32) (&acc[0][0])[t] = 0.f;
    for (int t = tid; t < NW * BB;      t += NW * 32) (&cnt[0][0])[t] = 0;
    __syncthreads();

    int c2    = e >> 3;
    int start = g_bin_start[e];
    int end   = g_bin_start[e + 1];
    float* A  = acc[warp];
    int*   C  = cnt[warp];

    for (int j0 = start + warp * 32; j0 < end; j0 += NW * 32) {
        int j = j0 + lane;
        bool v = (j < end);
        int packed = v ? g_sorted[j] : 0;
        int c0 = packed & 31;
        int c1 = packed >> 5;

        float4 x0, x1, x2, x3;
        if (v) {
            const float4* xp = (const float4*)(nodes + (c1 * SS + c2) * 16);
            x0 = xp[0]; x1 = xp[1]; x2 = xp[2]; x3 = xp[3];
        } else {
            x0 = x1 = x2 = x3 = make_float4(0.f, 0.f, 0.f, 0.f);
        }

        // layer 1: h[o] = relu(b0[o] + sum_i W0[o][i]*x[i])
        float h[32];
        #pragma unroll
        for (int o = 0; o < 32; o++) {
            const float4* w = (const float4*)(sW0 + o * 16);
            float4 w0 = w[0], w1 = w[1], w2 = w[2], w3 = w[3];
            float s = sb0[o];
            s = fmaf(w0.x, x0.x, s); s = fmaf(w0.y, x0.y, s);
            s = fmaf(w0.z, x0.z, s); s = fmaf(w0.w, x0.w, s);
            s = fmaf(w1.x, x1.x, s); s = fmaf(w1.y, x1.y, s);
            s = fmaf(w1.z, x1.z, s); s = fmaf(w1.w, x1.w, s);
            s = fmaf(w2.x, x2.x, s); s = fmaf(w2.y, x2.y, s);
            s = fmaf(w2.z, x2.z, s); s = fmaf(w2.w, x2.w, s);
            s = fmaf(w3.x, x3.x, s); s = fmaf(w3.y, x3.y, s);
            s = fmaf(w3.z, x3.z, s); s = fmaf(w3.w, x3.w, s);
            h[o] = fmaxf(s, 0.f);
        }

        // layer 2 + accumulate: g[o] = relu(b1[o] + sum_i W1[o][i]*h[i])
        #pragma unroll 8
        for (int o = 0; o < 32; o++) {
            const float4* w = (const float4*)(sW1 + o * 32);
            float s = sb1[o];
            #pragma unroll
            for (int q = 0; q < 8; q++) {
                float4 ww = w[q];
                s = fmaf(ww.x, h[q * 4 + 0], s);
                s = fmaf(ww.y, h[q * 4 + 1], s);
                s = fmaf(ww.z, h[q * 4 + 2], s);
                s = fmaf(ww.w, h[q * 4 + 3], s);
            }
            if (v) atomicAdd(&A[o * 32 + c0], fmaxf(s, 0.f));
        }
        if (v) atomicAdd(&C[c0], 1);
    }
    __syncthreads();

    // ---- totals + stage output weights (transposed; reuse sW0/sW1) ----
    if (tid < BB) {
        int s = 0;
        #pragma unroll
        for (int w = 0; w < NW; w++) s += cnt[w][tid];
        scnt[tid] = s;
    }
    for (int t = tid; t < 1024; t += NW * 32) {
        int o = t >> 5, i = t & 31;
        sW1[i * 32 + o] = oW0[e * 1024 + t];   // out_core0 [o][i] -> [i][o]
    }
    for (int t = tid; t < 512; t += NW * 32) {
        int o = t >> 5, i = t & 31;
        sW0[i * 16 + o] = oW1[e * 512 + t];    // out_core1 [o][i] (16x32) -> [i][o]
    }
    if (tid < 32) sb0[tid] = ob0[e * 32 + tid];
    if (tid < 16) sb1[tid] = ob1[e * 16 + tid];
    __syncthreads();

    // ---- mean ----
    for (int t = tid; t < BB * 32; t += NW * 32) {
        int b_ = t >> 5, i = t & 31;
        float s = 0.f;
        #pragma unroll
        for (int w = 0; w < NW; w++) s += acc[w][i * 32 + b_];
        int c = scnt[b_];
        ef[t] = (c > 0) ? s / (float)c : 0.f;
    }
    __syncthreads();

    // ---- out layer 1 ----
    for (int t = tid; t < BB * 32; t += NW * 32) {
        int b_ = t >> 5, o = t & 31;
        float s = sb0[o];
        #pragma unroll
        for (int i = 0; i < 32; i++)
            s = fmaf(sW1[i * 32 + o], ef[b_ * 32 + i], s);
        hh[t] = fmaxf(s, 0.f);
    }
    __syncthreads();

    // ---- out layer 2 + store ----
    for (int t = tid; t < BB * 16; t += NW * 32) {
        int b_ = t >> 4, o = t & 15;
        float s = sb1[o];
        #pragma unroll
        for (int i = 0; i < 32; i++)
            s = fmaf(sW0[i * 16 + o], hh[b_ * 32 + i], s);
        out[(b_ * NEIDX + e) * 16 + o] = fmaxf(s, 0.f);
    }
}

// ---------------- launch ----------------
extern "C" void kernel_launch(void* const* d_in, const int* in_sizes, int n_in,
                              void* d_out, int out_size) {
    const float* nodes = (const float*)d_in[0];
    const float* ic0   = (const float*)d_in[1];
    const float* ib0   = (const float*)d_in[2];
    const float* ic1   = (const float*)d_in[3];
    const float* ib1   = (const float*)d_in[4];
    const float* oc0   = (const float*)d_in[5];
    const float* ob0   = (const float*)d_in[6];
    const float* oc1   = (const float*)d_in[7];
    const float* ob1   = (const float*)d_in[8];
    const int4*  inc   = (const int4*)d_in[9];
    int E = in_sizes[9] / 4;
    float* out = (float*)d_out;

    k_zero<<<1, NEIDX>>>();
    k_hist<<<NBIN_CTAS, 512>>>(inc, E);
    k_scan<<<1, NEIDX>>>();
    k_scatter<<<NBIN_CTAS, 512>>>(inc, E);
    k_fused<<<NEIDX, NW * 32>>>(nodes, ic0, ib0, ic1, ib1,
                                oc0, ob0, oc1, ob1, out);
}

// round 4
// speedup vs baseline: 2.1251x; 1.5581x over previous
#include <cuda_runtime.h>
#include <cuda_bf16.h>

#define BB      32      // batch
#define SS      64      // S
#define DD      8       // D
#define NEIDX   512     // S*D distinct weight indices
#define EMAX    150000
#define NW      4       // warps per CTA in fused kernel
#define NBC     128     // binning CTAs

// ---------------- device scratch ----------------
__device__ int g_part[NBC][NEIDX];       // per-CTA partial histograms
__device__ int g_base[NBC][NEIDX];       // per-(CTA,bin) exclusive base within bin
__device__ int g_bin_start[NEIDX + 1];
__device__ int g_sorted[EMAX];           // packed: c0 | (c1<<5)

// ---------------- K1: per-CTA histogram (SMEM atomics only) ----------------
__global__ __launch_bounds__(512) void k_hist(const int4* __restrict__ inc, int E) {
    __shared__ int sh[NEIDX];
    int tid = threadIdx.x;
    sh[tid] = 0;
    __syncthreads();
    int per = (E + NBC - 1) / NBC;
    int beg = blockIdx.x * per;
    int end = min(beg + per, E);
    for (int i = beg + tid; i < end; i += 512) {
        int4 r = inc[i];
        atomicAdd(&sh[r.z * DD + r.w], 1);
    }
    __syncthreads();
    g_part[blockIdx.x][tid] = sh[tid];
}

// ---------------- K2: scan (single CTA): per-bin base over CTAs + bin_start ----
__global__ __launch_bounds__(NEIDX) void k_scan() {
    __shared__ int s[NEIDX];
    int t = threadIdx.x;
    // serial scan across CTAs for this bin (loads are independent -> pipelined)
    int run = 0;
    #pragma unroll 8
    for (int c = 0; c < NBC; c++) {
        int v = g_part[c][t];
        g_base[c][t] = run;
        run += v;
    }
    // cross-bin exclusive scan of totals
    s[t] = run;
    __syncthreads();
    for (int off = 1; off < NEIDX; off <<= 1) {
        int x = (t >= off) ? s[t - off] : 0;
        __syncthreads();
        s[t] += x;
        __syncthreads();
    }
    g_bin_start[t + 1] = s[t];
    if (t == 0) g_bin_start[0] = 0;
}

// ---------------- K3: scatter (SMEM cursors, zero global atomics) ----------------
__global__ __launch_bounds__(512) void k_scatter(const int4* __restrict__ inc, int E) {
    __shared__ int sc[NEIDX];
    int tid = threadIdx.x;
    sc[tid] = g_bin_start[tid] + g_base[blockIdx.x][tid];
    __syncthreads();
    int per = (E + NBC - 1) / NBC;     // must mirror k_hist slicing exactly
    int beg = blockIdx.x * per;
    int end = min(beg + per, E);
    for (int i = beg + tid; i < end; i += 512) {
        int4 r = inc[i];
        int b = r.z * DD + r.w;
        int pos = atomicAdd(&sc[b], 1);            // SMEM atomic only
        g_sorted[pos] = r.x | (r.y << 5);
    }
}

// ---------------- K4: fused edge MLP + segment mean + output MLP ----------------
// One CTA per eidx, 4 warps. Edge-per-lane compute (weights broadcast from
// SMEM). NO shared atomics: per-lane outputs are staged in a padded per-warp
// buffer, then a 32-step lane=channel reduce loop does plain conflict-free
// RMW into acc[c0][o] (same-warp program order => race-free).
__global__ __launch_bounds__(NW * 32) void k_fused(
    const float* __restrict__ nodes,
    const float* __restrict__ W0,  const float* __restrict__ b0,
    const float* __restrict__ W1,  const float* __restrict__ b1,
    const float* __restrict__ oW0, const float* __restrict__ ob0,
    const float* __restrict__ oW1, const float* __restrict__ ob1,
    float* __restrict__ out)
{
    __shared__ float sW0[512];             // in_core0 [o][i] 32x16 (broadcast reads)
    __shared__ float sW1[1024];            // in_core1 [o][i] 32x32
    __shared__ float sb0[32], sb1[32];
    __shared__ float acc[NW][BB * 32];     // [warp][c0*32 + o]
    __shared__ int   cnt[NW][BB];
    __shared__ int   scnt[BB];
    __shared__ float stage[NW][33 * 32];   // per-warp staging; reused as ef/hh later

    int e    = blockIdx.x;
    int tid  = threadIdx.x;
    int warp = tid >> 5, lane = tid & 31;

    for (int t = tid; t < 512;  t += NW * 32) sW0[t] = W0[e * 512 + t];
    for (int t = tid; t < 1024; t += NW * 32) sW1[t] = W1[e * 1024 + t];
    if (tid < 32) { sb0[tid] = b0[e * 32 + tid]; sb1[tid] = b1[e * 32 + tid]; }
    for (int t = tid; t < NW * BB * 32; t += NW * 32) (&acc[0][0])[t] = 0.f;
    for (int t = tid; t < NW * BB;      t += NW * 32) (&cnt[0][0])[t] = 0;
    __syncthreads();

    int c2    = e >> 3;
    int start = g_bin_start[e];
    int end   = g_bin_start[e + 1];
    float* A  = acc[warp];
    float* ST = stage[warp];

    for (int j0 = start + warp * 32; j0 < end; j0 += NW * 32) {
        int j = j0 + lane;
        bool v = (j < end);
        int packed = v ? g_sorted[j] : -1;
        int c0 = packed & 31;
        int c1 = (packed >> 5) & 1023;

        float4 x0, x1, x2, x3;
        if (v) {
            const float4* xp = (const float4*)(nodes + (c1 * SS + c2) * 16);
            x0 = xp[0]; x1 = xp[1]; x2 = xp[2]; x3 = xp[3];
        } else {
            x0 = x1 = x2 = x3 = make_float4(0.f, 0.f, 0.f, 0.f);
        }

        // layer 1: h[o] = relu(b0[o] + sum_i W0[o][i]*x[i])
        float h[32];
        #pragma unroll
        for (int o = 0; o < 32; o++) {
            const float4* w = (const float4*)(sW0 + o * 16);
            float4 w0 = w[0], w1 = w[1], w2 = w[2], w3 = w[3];
            float s = sb0[o];
            s = fmaf(w0.x, x0.x, s); s = fmaf(w0.y, x0.y, s);
            s = fmaf(w0.z, x0.z, s); s = fmaf(w0.w, x0.w, s);
            s = fmaf(w1.x, x1.x, s); s = fmaf(w1.y, x1.y, s);
            s = fmaf(w1.z, x1.z, s); s = fmaf(w1.w, x1.w, s);
            s = fmaf(w2.x, x2.x, s); s = fmaf(w2.y, x2.y, s);
            s = fmaf(w2.z, x2.z, s); s = fmaf(w2.w, x2.w, s);
            s = fmaf(w3.x, x3.x, s); s = fmaf(w3.y, x3.y, s);
            s = fmaf(w3.z, x3.z, s); s = fmaf(w3.w, x3.w, s);
            h[o] = fmaxf(s, 0.f);
        }

        // layer 2 -> staged to SMEM (stride-33: bank (lane+o)%32, conflict-free)
        #pragma unroll 8
        for (int o = 0; o < 32; o++) {
            const float4* w = (const float4*)(sW1 + o * 32);
            float s = sb1[o];
            #pragma unroll
            for (int q = 0; q < 8; q++) {
                float4 ww = w[q];
                s = fmaf(ww.x, h[q * 4 + 0], s);
                s = fmaf(ww.y, h[q * 4 + 1], s);
                s = fmaf(ww.z, h[q * 4 + 2], s);
                s = fmaf(ww.w, h[q * 4 + 3], s);
            }
            ST[lane * 33 + o] = v ? fmaxf(s, 0.f) : 0.f;
        }
        if (v) atomicAdd(&cnt[warp][c0], 1);
        __syncwarp();

        // reduce: lane = output channel o. Per step: c0 uniform -> bank = lane,
        // conflict-free; RMW ordered by same-warp program order.
        #pragma unroll
        for (int j2 = 0; j2 < 32; j2++) {
            int pk = __shfl_sync(0xffffffffu, packed, j2);
            if (pk >= 0) {
                int c0j = pk & 31;
                A[c0j * 32 + lane] += ST[j2 * 33 + lane];
            }
        }
        __syncwarp();
    }
    __syncthreads();

    // ---- totals + stage output weights (transposed; reuse sW0/sW1) ----
    float* ef = &stage[0][0];      // 1024 floats
    float* hh = &stage[2][0];      // 1024 floats (disjoint: offset 2112)

    if (tid < BB) {
        int s = 0;
        #pragma unroll
        for (int w = 0; w < NW; w++) s += cnt[w][tid];
        scnt[tid] = s;
    }
    for (int t = tid; t < 1024; t += NW * 32) {
        int o = t >> 5, i = t & 31;
        sW1[i * 32 + o] = oW0[e * 1024 + t];   // out_core0 [o][i] -> [i][o]
    }
    for (int t = tid; t < 512; t += NW * 32) {
        int o = t >> 5, i = t & 31;
        sW0[i * 16 + o] = oW1[e * 512 + t];    // out_core1 [o][i] (16x32) -> [i][o]
    }
    if (tid < 32) sb0[tid] = ob0[e * 32 + tid];
    if (tid < 16) sb1[tid] = ob1[e * 16 + tid];
    __syncthreads();

    // ---- mean ----
    for (int t = tid; t < BB * 32; t += NW * 32) {
        int b_ = t >> 5, i = t & 31;
        float s = 0.f;
        #pragma unroll
        for (int w = 0; w < NW; w++) s += acc[w][b_ * 32 + i];
        int c = scnt[b_];
        ef[t] = (c > 0) ? s / (float)c : 0.f;
    }
    __syncthreads();

    // ---- out layer 1 ----
    for (int t = tid; t < BB * 32; t += NW * 32) {
        int b_ = t >> 5, o = t & 31;
        float s = sb0[o];
        #pragma unroll
        for (int i = 0; i < 32; i++)
            s = fmaf(sW1[i * 32 + o], ef[b_ * 32 + i], s);
        hh[t] = fmaxf(s, 0.f);
    }
    __syncthreads();

    // ---- out layer 2 + store ----
    for (int t = tid; t < BB * 16; t += NW * 32) {
        int b_ = t >> 4, o = t & 15;
        float s = sb1[o];
        #pragma unroll
        for (int i = 0; i < 32; i++)
            s = fmaf(sW0[i * 16 + o], hh[b_ * 32 + i], s);
        out[(b_ * NEIDX + e) * 16 + o] = fmaxf(s, 0.f);
    }
}

// ---------------- launch ----------------
extern "C" void kernel_launch(void* const* d_in, const int* in_sizes, int n_in,
                              void* d_out, int out_size) {
    const float* nodes = (const float*)d_in[0];
    const float* ic0   = (const float*)d_in[1];
    const float* ib0   = (const float*)d_in[2];
    const float* ic1   = (const float*)d_in[3];
    const float* ib1   = (const float*)d_in[4];
    const float* oc0   = (const float*)d_in[5];
    const float* ob0   = (const float*)d_in[6];
    const float* oc1   = (const float*)d_in[7];
    const float* ob1   = (const float*)d_in[8];
    const int4*  inc   = (const int4*)d_in[9];
    int E = in_sizes[9] / 4;
    float* out = (float*)d_out;

    k_hist<<<NBC, 512>>>(inc, E);
    k_scan<<<1, NEIDX>>>();
    k_scatter<<<NBC, 512>>>(inc, E);
    k_fused<<<NEIDX, NW * 32>>>(nodes, ic0, ib0, ic1, ib1,
                                oc0, ob0, oc1, ob1, out);
}